// round 1
// baseline (speedup 1.0000x reference)
#include <cuda_runtime.h>
#include <math.h>

// Problem constants (fixed by the dataset)
#define NNODES 50000
#define NEDGES 600000
#define NREL   8
#define NBASIS 32
#define GDIM   128
#define HD1    128
#define HD2    128
#define RN     (NREL * NNODES)          // 400000 (relation,dst) segments
#define SCAN_B 1024
#define NSCAN  ((RN + SCAN_B - 1) / SCAN_B)   // 391

// ---------------- scratch (static __device__ — no allocation allowed) ----------------
static __device__ __align__(16) float d_Wbig[NREL * GDIM * HD1];        // [1024][128]
static __device__ __align__(16) float d_Wcat[HD1 * 512];                // [128][k|q|v|s]
static __device__ __align__(16) float d_bcat[512];
static __device__ __align__(16) float d_Abig[(size_t)NNODES * NREL * GDIM]; // [N][1024]
static __device__ __align__(16) float d_h[(size_t)NNODES * HD1];
static __device__ __align__(16) float d_kqvs[(size_t)NNODES * 512];
static __device__ int d_cnt[RN];
static __device__ int d_off[RN + 1];
static __device__ int d_cur[RN];
static __device__ int d_ssrc[NEDGES];
static __device__ int d_part[SCAN_B];
static __device__ int d_ppre[SCAN_B];

// ---------------- tiny helpers ----------------
__device__ __forceinline__ float sigf(float z) { return 1.0f / (1.0f + __expf(-z)); }

// W[r,i,o] = sum_b comp[r,b] * basis[b,i,o], stored as Wbig[(r*128+i)*128+o]
__global__ void build_W(const float* __restrict__ comp, const float* __restrict__ basis) {
    int idx = blockIdx.x * blockDim.x + threadIdx.x;     // over 8*128*128
    if (idx >= NREL * GDIM * HD1) return;
    int o = idx & 127;
    int i = (idx >> 7) & 127;
    int r = idx >> 14;
    float s = 0.0f;
    #pragma unroll
    for (int b = 0; b < NBASIS; b++)
        s += comp[r * NBASIS + b] * basis[(b * GDIM + i) * HD1 + o];
    d_Wbig[idx] = s;
}

// Pack [w_key | w_query | w_value | w_skip] into Wcat[128][512], biases into bcat[512]
__global__ void pack_stage2(const float* wk, const float* bk, const float* wq, const float* bq,
                            const float* wv, const float* bv, const float* ws, const float* bs) {
    int idx = blockIdx.x * blockDim.x + threadIdx.x;
    if (idx >= HD1 * 512) return;
    int row = idx >> 9;
    int c   = idx & 511;
    int sel = c >> 7;
    int cc  = c & 127;
    const float* W = (sel == 0) ? wk : (sel == 1) ? wq : (sel == 2) ? wv : ws;
    d_Wcat[idx] = W[row * HD2 + cc];
    if (row == 0) {
        const float* B = (sel == 0) ? bk : (sel == 1) ? bq : (sel == 2) ? bv : bs;
        d_bcat[c] = B[cc];
    }
}

__global__ void zero_cnt() {
    int i = blockIdx.x * blockDim.x + threadIdx.x;
    if (i < RN) d_cnt[i] = 0;
}

__global__ void count_edges(const int* __restrict__ ei, const int* __restrict__ etype) {
    int e = blockIdx.x * blockDim.x + threadIdx.x;
    if (e >= NEDGES) return;
    int dst = ei[NEDGES + e];
    int key = dst * NREL + etype[e];
    atomicAdd(&d_cnt[key], 1);
}

// ---- 3-kernel exclusive prefix scan over d_cnt -> d_off ----
__global__ void scan_blocksum() {
    __shared__ int s[SCAN_B];
    int tid = threadIdx.x;
    int gid = blockIdx.x * SCAN_B + tid;
    s[tid] = (gid < RN) ? d_cnt[gid] : 0;
    __syncthreads();
    for (int o = SCAN_B / 2; o > 0; o >>= 1) {
        if (tid < o) s[tid] += s[tid + o];
        __syncthreads();
    }
    if (tid == 0) d_part[blockIdx.x] = s[0];
}

__global__ void scan_partials() {
    __shared__ int s[SCAN_B];
    int tid = threadIdx.x;
    int v = (tid < NSCAN) ? d_part[tid] : 0;
    s[tid] = v;
    __syncthreads();
    for (int o = 1; o < SCAN_B; o <<= 1) {
        int t = (tid >= o) ? s[tid - o] : 0;
        __syncthreads();
        s[tid] += t;
        __syncthreads();
    }
    d_ppre[tid] = s[tid] - v;   // exclusive prefix of block sums
}

__global__ void scan_final() {
    __shared__ int s[SCAN_B];
    int tid = threadIdx.x;
    int gid = blockIdx.x * SCAN_B + tid;
    int v = (gid < RN) ? d_cnt[gid] : 0;
    s[tid] = v;
    __syncthreads();
    for (int o = 1; o < SCAN_B; o <<= 1) {
        int t = (tid >= o) ? s[tid - o] : 0;
        __syncthreads();
        s[tid] += t;
        __syncthreads();
    }
    int ex = s[tid] - v + d_ppre[blockIdx.x];
    if (gid < RN) {
        d_off[gid] = ex;
        d_cur[gid] = ex;
        if (gid == RN - 1) d_off[RN] = ex + v;
    }
}

__global__ void scatter_edges(const int* __restrict__ ei, const int* __restrict__ etype) {
    int e = blockIdx.x * blockDim.x + threadIdx.x;
    if (e >= NEDGES) return;
    int src = ei[e];
    int dst = ei[NEDGES + e];
    int key = dst * NREL + etype[e];
    int pos = atomicAdd(&d_cur[key], 1);
    d_ssrc[pos] = src;
}

// One warp per (dst, rel) segment: Abig[dst][r*128 + c] = mean of x[src] over segment
__global__ void agg_segments(const float* __restrict__ x) {
    int seg  = blockIdx.x * 8 + (threadIdx.x >> 5);
    if (seg >= RN) return;
    int lane = threadIdx.x & 31;
    int beg = d_off[seg];
    int end = d_off[seg + 1];
    int dst = seg >> 3;
    int r   = seg & 7;
    const float4* x4 = reinterpret_cast<const float4*>(x);
    float4 acc = make_float4(0.f, 0.f, 0.f, 0.f);
    for (int e = beg; e < end; e++) {
        int s = d_ssrc[e];
        float4 v = __ldg(&x4[s * 32 + lane]);
        acc.x += v.x; acc.y += v.y; acc.z += v.z; acc.w += v.w;
    }
    float inv = (end > beg) ? 1.0f / (float)(end - beg) : 0.0f;
    acc.x *= inv; acc.y *= inv; acc.z *= inv; acc.w *= inv;
    float4* A4 = reinterpret_cast<float4*>(d_Abig);
    A4[dst * 256 + r * 32 + lane] = acc;
}

// ---------------- fp32 SGEMM: C[M,Nn] = A[M,K] @ B[K,Nn] (+ C_old) (+ bias[col]) ----------------
__global__ void sgemm(const float* __restrict__ A, const float* __restrict__ B,
                      const float* __restrict__ bias, float* __restrict__ C,
                      int M, int K, int Nn, int accFlag, int biasFlag) {
    __shared__ float As[16][132];   // padded, transposed A tile (k-major)
    __shared__ float Bs[16][128];

    int tid = threadIdx.x;
    int m0 = blockIdx.y * 128;
    int n0 = blockIdx.x * 128;

    int aRow = tid >> 2;           // 0..63
    int aCol = (tid & 3) << 2;     // 0,4,8,12
    int bRow = tid >> 5;           // 0..7
    int bCol = (tid & 31) << 2;    // 0..124

    int tm = (tid >> 4) << 3;      // 0..120
    int tn = (tid & 15) << 3;      // 0..120

    float acc[8][8] = {};

    for (int k0 = 0; k0 < K; k0 += 16) {
        #pragma unroll
        for (int h = 0; h < 2; h++) {
            int r = aRow + h * 64;
            int gr = m0 + r;
            float4 v = (gr < M) ? *(const float4*)(A + (size_t)gr * K + k0 + aCol)
                                : make_float4(0.f, 0.f, 0.f, 0.f);
            As[aCol + 0][r] = v.x;
            As[aCol + 1][r] = v.y;
            As[aCol + 2][r] = v.z;
            As[aCol + 3][r] = v.w;
        }
        #pragma unroll
        for (int h = 0; h < 2; h++) {
            int r = bRow + h * 8;
            float4 v = *(const float4*)(B + (size_t)(k0 + r) * Nn + n0 + bCol);
            *(float4*)&Bs[r][bCol] = v;
        }
        __syncthreads();
        #pragma unroll
        for (int kk = 0; kk < 16; kk++) {
            float a[8], b[8];
            *(float4*)(a)     = *(const float4*)&As[kk][tm];
            *(float4*)(a + 4) = *(const float4*)&As[kk][tm + 4];
            *(float4*)(b)     = *(const float4*)&Bs[kk][tn];
            *(float4*)(b + 4) = *(const float4*)&Bs[kk][tn + 4];
            #pragma unroll
            for (int i = 0; i < 8; i++)
                #pragma unroll
                for (int j = 0; j < 8; j++)
                    acc[i][j] += a[i] * b[j];
        }
        __syncthreads();
    }

    #pragma unroll
    for (int i = 0; i < 8; i++) {
        int gr = m0 + tm + i;
        if (gr >= M) continue;
        #pragma unroll
        for (int j = 0; j < 8; j += 4) {
            size_t off = (size_t)gr * Nn + n0 + tn + j;
            float4 v = make_float4(acc[i][j], acc[i][j + 1], acc[i][j + 2], acc[i][j + 3]);
            if (accFlag) {
                float4 o = *(const float4*)(C + off);
                v.x += o.x; v.y += o.y; v.z += o.z; v.w += o.w;
            }
            if (biasFlag) {
                int bc = n0 + tn + j;
                v.x += bias[bc]; v.y += bias[bc + 1]; v.z += bias[bc + 2]; v.w += bias[bc + 3];
            }
            *(float4*)(C + off) = v;
        }
    }
}

// One warp per dst: out[dst] = skip + sum_{e -> dst} sigmoid(k[dst]+q[src]) * v[src]
__global__ void gate_kernel(float* __restrict__ out) {
    int dst  = blockIdx.x * 8 + (threadIdx.x >> 5);
    if (dst >= NNODES) return;
    int lane = threadIdx.x & 31;
    const float4* kq = reinterpret_cast<const float4*>(d_kqvs);   // 128 float4 per node row
    float4 kd  = kq[dst * 128 + lane];          // k    : cols 0..127
    float4 acc = kq[dst * 128 + 96 + lane];     // skip : cols 384..511 (bias already added)
    int beg = d_off[dst * NREL];
    int end = d_off[dst * NREL + NREL];
    for (int e = beg; e < end; e++) {
        int s = d_ssrc[e];
        float4 qv = __ldg(&kq[s * 128 + 32 + lane]);   // q : cols 128..255
        float4 vv = __ldg(&kq[s * 128 + 64 + lane]);   // v : cols 256..383
        acc.x += vv.x * sigf(kd.x + qv.x);
        acc.y += vv.y * sigf(kd.y + qv.y);
        acc.z += vv.z * sigf(kd.z + qv.z);
        acc.w += vv.w * sigf(kd.w + qv.w);
    }
    reinterpret_cast<float4*>(out)[dst * 32 + lane] = acc;
}

// ---------------- launcher ----------------
extern "C" void kernel_launch(void* const* d_in, const int* in_sizes, int n_in,
                              void* d_out, int out_size) {
    const float* x     = (const float*)d_in[0];
    const int*   ei    = (const int*)  d_in[1];
    // d_in[2] = edge_norm: unused by the reference
    const int*   etype = (const int*)  d_in[3];
    const float* basis = (const float*)d_in[4];
    const float* comp  = (const float*)d_in[5];
    const float* root  = (const float*)d_in[6];
    const float* bias1 = (const float*)d_in[7];
    const float* wk = (const float*)d_in[8];  const float* bk = (const float*)d_in[9];
    const float* wq = (const float*)d_in[10]; const float* bq = (const float*)d_in[11];
    const float* wv = (const float*)d_in[12]; const float* bv = (const float*)d_in[13];
    const float* ws = (const float*)d_in[14]; const float* bs = (const float*)d_in[15];
    float* out = (float*)d_out;

    // Resolve scratch addresses for GEMM operands (pure lookup, capture-safe)
    void *pAbig = nullptr, *pWbig = nullptr, *ph = nullptr, *pkqvs = nullptr,
         *pWcat = nullptr, *pbcat = nullptr;
    cudaGetSymbolAddress(&pAbig, d_Abig);
    cudaGetSymbolAddress(&pWbig, d_Wbig);
    cudaGetSymbolAddress(&ph,    d_h);
    cudaGetSymbolAddress(&pkqvs, d_kqvs);
    cudaGetSymbolAddress(&pWcat, d_Wcat);
    cudaGetSymbolAddress(&pbcat, d_bcat);

    // Weights
    build_W<<<(NREL * GDIM * HD1 + 255) / 256, 256>>>(comp, basis);
    pack_stage2<<<(HD1 * 512 + 255) / 256, 256>>>(wk, bk, wq, bq, wv, bv, ws, bs);

    // CSR over key = dst*8 + rel (serves both RGCN means and ResGated dst segments)
    zero_cnt<<<(RN + 255) / 256, 256>>>();
    count_edges<<<(NEDGES + 255) / 256, 256>>>(ei, etype);
    scan_blocksum<<<NSCAN, SCAN_B>>>();
    scan_partials<<<1, SCAN_B>>>();
    scan_final<<<NSCAN, SCAN_B>>>();
    scatter_edges<<<(NEDGES + 255) / 256, 256>>>(ei, etype);

    // Per-(rel,dst) mean of x[src] -> Abig[N][1024] (writes every segment, incl. zeros)
    agg_segments<<<RN / 8, 256>>>(x);

    // h = x @ root + bias1 ; h += Abig @ Wbig
    sgemm<<<dim3(1, (NNODES + 127) / 128), 256>>>(x, root, bias1, (float*)ph,
                                                  NNODES, GDIM, HD1, 0, 1);
    sgemm<<<dim3(1, (NNODES + 127) / 128), 256>>>((const float*)pAbig, (const float*)pWbig,
                                                  nullptr, (float*)ph,
                                                  NNODES, NREL * GDIM, HD1, 1, 0);

    // kqvs = h @ [Wk|Wq|Wv|Wskip] + [bk|bq|bv|bskip]
    sgemm<<<dim3(4, (NNODES + 127) / 128), 256>>>((const float*)ph, (const float*)pWcat,
                                                  (const float*)pbcat, (float*)pkqvs,
                                                  NNODES, HD1, 512, 0, 1);

    // out = skip + sum sigmoid(k_dst + q_src) * v_src
    gate_kernel<<<NNODES / 8, 256>>>(out);
}

// round 3
// speedup vs baseline: 1.2516x; 1.2516x over previous
#include <cuda_runtime.h>
#include <cuda_bf16.h>
#include <mma.h>
#include <cstdint>

using namespace nvcuda;

#define NNODES 50000
#define NEDGES 600000
#define NREL   8
#define NBASIS 32
#define RN     (NREL * NNODES)
#define SCAN_B 1024
#define NSCAN  ((RN + SCAN_B - 1) / SCAN_B)
#define NK     1152                      // GEMM1 K: 8*128 + 128 (root)
#define MT     ((NNODES + 127) / 128)    // 391 M-tiles
#define MPAD   (MT * 128)                // 50048 padded rows

// ---------------- static device scratch ----------------
static __device__ __align__(16) __nv_bfloat16 d_Ahi[(size_t)NNODES * NK];
static __device__ __align__(16) __nv_bfloat16 d_Alo[(size_t)NNODES * NK];
static __device__ __align__(16) __nv_bfloat16 d_Bhi[128 * NK];   // [n][k]
static __device__ __align__(16) __nv_bfloat16 d_Blo[128 * NK];
static __device__ __align__(16) __nv_bfloat16 d_Chi[512 * 128];  // [n][k]
static __device__ __align__(16) __nv_bfloat16 d_Clo[512 * 128];
static __device__ __align__(16) float d_bcat[512];
static __device__ __align__(16) __nv_bfloat16 d_hhi[(size_t)NNODES * 128];
static __device__ __align__(16) __nv_bfloat16 d_hlo[(size_t)NNODES * 128];
static __device__ __align__(16) float d_C1[(size_t)MPAD * 128];   // raw h
static __device__ __align__(16) float d_C2[(size_t)MPAD * 512];   // raw kqvs
static __device__ __align__(16) float d_kskip[(size_t)NNODES * 256]; // [k | skip]
static __device__ __align__(16) float d_qv[(size_t)NNODES * 256];    // [q | v]
static __device__ int d_cnt[RN];
static __device__ int d_off[RN + 1];
static __device__ int d_cur[RN];
static __device__ int d_ssrc[NEDGES];
static __device__ int d_part[SCAN_B];
static __device__ int d_ppre[SCAN_B];

// ---------------- helpers ----------------
__device__ __forceinline__ void split2(float v, __nv_bfloat16& hi, __nv_bfloat16& lo) {
    hi = __float2bfloat16(v);
    lo = __float2bfloat16(v - __bfloat162float(hi));
}
__device__ __forceinline__ float sigf(float z) { return 1.0f / (1.0f + __expf(-z)); }

// ---------------- weight prep ----------------
__global__ void build_BT(const float* __restrict__ comp, const float* __restrict__ basis,
                         const float* __restrict__ root) {
    int idx = blockIdx.x * blockDim.x + threadIdx.x;
    if (idx >= 128 * NK) return;
    int n = idx / NK, k = idx % NK;
    float w;
    if (k < 1024) {
        int r = k >> 7, i = k & 127;
        float s = 0.0f;
        #pragma unroll
        for (int b = 0; b < NBASIS; b++)
            s += comp[r * NBASIS + b] * basis[(b * 128 + i) * 128 + n];
        w = s;
    } else {
        w = root[(k - 1024) * 128 + n];
    }
    __nv_bfloat16 hi, lo; split2(w, hi, lo);
    d_Bhi[idx] = hi; d_Blo[idx] = lo;
}

__global__ void pack_CT(const float* wk, const float* bk, const float* wq, const float* bq,
                        const float* wv, const float* bv, const float* ws, const float* bs) {
    int idx = blockIdx.x * blockDim.x + threadIdx.x;
    if (idx >= 512 * 128) return;
    int n = idx >> 7, k = idx & 127;
    int sel = n >> 7, cc = n & 127;
    const float* W = (sel == 0) ? wk : (sel == 1) ? wq : (sel == 2) ? wv : ws;
    __nv_bfloat16 hi, lo; split2(W[k * 128 + cc], hi, lo);
    d_Chi[idx] = hi; d_Clo[idx] = lo;
    if (k == 0) {
        const float* B = (sel == 0) ? bk : (sel == 1) ? bq : (sel == 2) ? bv : bs;
        d_bcat[n] = B[cc];
    }
}

// ---------------- CSR build ----------------
__global__ void zero_cnt() {
    int i = blockIdx.x * blockDim.x + threadIdx.x;
    if (i < RN) d_cnt[i] = 0;
}
__global__ void count_edges(const int* __restrict__ ei, const int* __restrict__ etype) {
    int e = blockIdx.x * blockDim.x + threadIdx.x;
    if (e >= NEDGES) return;
    atomicAdd(&d_cnt[ei[NEDGES + e] * NREL + etype[e]], 1);
}
__global__ void scan_blocksum() {
    __shared__ int s[SCAN_B];
    int tid = threadIdx.x, gid = blockIdx.x * SCAN_B + tid;
    s[tid] = (gid < RN) ? d_cnt[gid] : 0;
    __syncthreads();
    for (int o = SCAN_B / 2; o > 0; o >>= 1) { if (tid < o) s[tid] += s[tid + o]; __syncthreads(); }
    if (tid == 0) d_part[blockIdx.x] = s[0];
}
__global__ void scan_partials() {
    __shared__ int s[SCAN_B];
    int tid = threadIdx.x;
    int v = (tid < NSCAN) ? d_part[tid] : 0;
    s[tid] = v; __syncthreads();
    for (int o = 1; o < SCAN_B; o <<= 1) {
        int t = (tid >= o) ? s[tid - o] : 0; __syncthreads();
        s[tid] += t; __syncthreads();
    }
    d_ppre[tid] = s[tid] - v;
}
__global__ void scan_final() {
    __shared__ int s[SCAN_B];
    int tid = threadIdx.x, gid = blockIdx.x * SCAN_B + tid;
    int v = (gid < RN) ? d_cnt[gid] : 0;
    s[tid] = v; __syncthreads();
    for (int o = 1; o < SCAN_B; o <<= 1) {
        int t = (tid >= o) ? s[tid - o] : 0; __syncthreads();
        s[tid] += t; __syncthreads();
    }
    int ex = s[tid] - v + d_ppre[blockIdx.x];
    if (gid < RN) {
        d_off[gid] = ex; d_cur[gid] = ex;
        if (gid == RN - 1) d_off[RN] = ex + v;
    }
}
__global__ void scatter_edges(const int* __restrict__ ei, const int* __restrict__ etype) {
    int e = blockIdx.x * blockDim.x + threadIdx.x;
    if (e >= NEDGES) return;
    int pos = atomicAdd(&d_cur[ei[NEDGES + e] * NREL + etype[e]], 1);
    d_ssrc[pos] = ei[e];
}

// ---------------- gather: per-(dst,rel) mean -> split-bf16 A cols 0..1023 ----------------
__global__ void agg_split(const float* __restrict__ x) {
    int seg = blockIdx.x * 8 + (threadIdx.x >> 5);
    if (seg >= RN) return;
    int lane = threadIdx.x & 31;
    int beg = d_off[seg], end = d_off[seg + 1];
    int dst = seg >> 3, r = seg & 7;
    const float4* x4 = reinterpret_cast<const float4*>(x);
    float4 acc = make_float4(0.f, 0.f, 0.f, 0.f);
    for (int e = beg; e < end; e++) {
        float4 v = __ldg(&x4[(size_t)d_ssrc[e] * 32 + lane]);
        acc.x += v.x; acc.y += v.y; acc.z += v.z; acc.w += v.w;
    }
    float inv = (end > beg) ? 1.0f / (float)(end - beg) : 0.0f;
    float vv[4] = { acc.x * inv, acc.y * inv, acc.z * inv, acc.w * inv };
    __align__(8) __nv_bfloat16 hi[4], lo[4];
    #pragma unroll
    for (int j = 0; j < 4; j++) split2(vv[j], hi[j], lo[j]);
    size_t b = (size_t)dst * NK + r * 128 + lane * 4;
    *(uint2*)&d_Ahi[b] = *(uint2*)hi;
    *(uint2*)&d_Alo[b] = *(uint2*)lo;
}

// x -> split-bf16 A cols 1024..1151 (root term)
__global__ void xsplit(const float* __restrict__ x) {
    int idx = blockIdx.x * blockDim.x + threadIdx.x;
    if (idx >= NNODES * 32) return;
    int row = idx >> 5, l = idx & 31;
    float4 v = reinterpret_cast<const float4*>(x)[(size_t)row * 32 + l];
    float vv[4] = { v.x, v.y, v.z, v.w };
    __align__(8) __nv_bfloat16 hi[4], lo[4];
    #pragma unroll
    for (int j = 0; j < 4; j++) split2(vv[j], hi[j], lo[j]);
    size_t b = (size_t)row * NK + 1024 + l * 4;
    *(uint2*)&d_Ahi[b] = *(uint2*)hi;
    *(uint2*)&d_Alo[b] = *(uint2*)lo;
}

// ---------------- wmma GEMMs: C = A_split @ B_split^T (3-product bf16 split) ----------------
// smem tile stride: 40 bf16 = 80 B (16B-aligned, bank-spread)
typedef wmma::fragment<wmma::matrix_a, 16, 16, 16, __nv_bfloat16, wmma::row_major> FragA;
typedef wmma::fragment<wmma::matrix_b, 16, 16, 16, __nv_bfloat16, wmma::col_major> FragB;
typedef wmma::fragment<wmma::accumulator, 16, 16, 16, float> FragC;

__global__ void __launch_bounds__(256) gemm1_wmma() {
    __shared__ __nv_bfloat16 sA[2][128][40];
    __shared__ __nv_bfloat16 sB[2][128][40];
    int tid = threadIdx.x, wid = tid >> 5;
    int m0 = blockIdx.x << 7;
    int wm = (wid & 3) << 5;    // warp row base (0..96)
    int wn = (wid >> 2) << 6;   // warp col base (0 or 64)

    FragC acc[2][4];
    #pragma unroll
    for (int i = 0; i < 2; i++)
        #pragma unroll
        for (int j = 0; j < 4; j++) wmma::fill_fragment(acc[i][j], 0.0f);

    for (int ch = 0; ch < NK / 32; ch++) {
        int k0 = ch << 5;
        for (int t = tid; t < 512; t += 256) {
            int row = t >> 2, c8 = (t & 3) << 3;
            int gr = m0 + row;
            uint4 vh = make_uint4(0, 0, 0, 0), vl = make_uint4(0, 0, 0, 0);
            if (gr < NNODES) {
                size_t ga = (size_t)gr * NK + k0 + c8;
                vh = *(const uint4*)(d_Ahi + ga);
                vl = *(const uint4*)(d_Alo + ga);
            }
            *(uint4*)&sA[0][row][c8] = vh;
            *(uint4*)&sA[1][row][c8] = vl;
            size_t gb = (size_t)row * NK + k0 + c8;
            *(uint4*)&sB[0][row][c8] = *(const uint4*)(d_Bhi + gb);
            *(uint4*)&sB[1][row][c8] = *(const uint4*)(d_Blo + gb);
        }
        __syncthreads();
        #pragma unroll
        for (int kk = 0; kk < 32; kk += 16) {
            FragA fah[2], fal[2];
            FragB fbh[4], fbl[4];
            #pragma unroll
            for (int i = 0; i < 2; i++) {
                wmma::load_matrix_sync(fah[i], &sA[0][wm + i * 16][kk], 40);
                wmma::load_matrix_sync(fal[i], &sA[1][wm + i * 16][kk], 40);
            }
            #pragma unroll
            for (int j = 0; j < 4; j++) {
                wmma::load_matrix_sync(fbh[j], &sB[0][wn + j * 16][kk], 40);
                wmma::load_matrix_sync(fbl[j], &sB[1][wn + j * 16][kk], 40);
            }
            #pragma unroll
            for (int i = 0; i < 2; i++)
                #pragma unroll
                for (int j = 0; j < 4; j++) {
                    wmma::mma_sync(acc[i][j], fah[i], fbh[j], acc[i][j]);
                    wmma::mma_sync(acc[i][j], fah[i], fbl[j], acc[i][j]);
                    wmma::mma_sync(acc[i][j], fal[i], fbh[j], acc[i][j]);
                }
        }
        __syncthreads();
    }
    #pragma unroll
    for (int i = 0; i < 2; i++)
        #pragma unroll
        for (int j = 0; j < 4; j++)
            wmma::store_matrix_sync(&d_C1[(size_t)(m0 + wm + i * 16) * 128 + wn + j * 16],
                                    acc[i][j], 128, wmma::mem_row_major);
}

__global__ void __launch_bounds__(256) gemm2_wmma() {
    __shared__ __nv_bfloat16 sA[2][128][40];
    __shared__ __nv_bfloat16 sB[2][128][40];
    int tid = threadIdx.x, wid = tid >> 5;
    int m0 = blockIdx.x << 7;
    int n0 = blockIdx.y << 7;
    int wm = (wid & 3) << 5;
    int wn = (wid >> 2) << 6;

    FragC acc[2][4];
    #pragma unroll
    for (int i = 0; i < 2; i++)
        #pragma unroll
        for (int j = 0; j < 4; j++) wmma::fill_fragment(acc[i][j], 0.0f);

    for (int ch = 0; ch < 4; ch++) {
        int k0 = ch << 5;
        for (int t = tid; t < 512; t += 256) {
            int row = t >> 2, c8 = (t & 3) << 3;
            int gr = m0 + row;
            uint4 vh = make_uint4(0, 0, 0, 0), vl = make_uint4(0, 0, 0, 0);
            if (gr < NNODES) {
                size_t ga = (size_t)gr * 128 + k0 + c8;
                vh = *(const uint4*)(d_hhi + ga);
                vl = *(const uint4*)(d_hlo + ga);
            }
            *(uint4*)&sA[0][row][c8] = vh;
            *(uint4*)&sA[1][row][c8] = vl;
            size_t gb = (size_t)(n0 + row) * 128 + k0 + c8;
            *(uint4*)&sB[0][row][c8] = *(const uint4*)(d_Chi + gb);
            *(uint4*)&sB[1][row][c8] = *(const uint4*)(d_Clo + gb);
        }
        __syncthreads();
        #pragma unroll
        for (int kk = 0; kk < 32; kk += 16) {
            FragA fah[2], fal[2];
            FragB fbh[4], fbl[4];
            #pragma unroll
            for (int i = 0; i < 2; i++) {
                wmma::load_matrix_sync(fah[i], &sA[0][wm + i * 16][kk], 40);
                wmma::load_matrix_sync(fal[i], &sA[1][wm + i * 16][kk], 40);
            }
            #pragma unroll
            for (int j = 0; j < 4; j++) {
                wmma::load_matrix_sync(fbh[j], &sB[0][wn + j * 16][kk], 40);
                wmma::load_matrix_sync(fbl[j], &sB[1][wn + j * 16][kk], 40);
            }
            #pragma unroll
            for (int i = 0; i < 2; i++)
                #pragma unroll
                for (int j = 0; j < 4; j++) {
                    wmma::mma_sync(acc[i][j], fah[i], fbh[j], acc[i][j]);
                    wmma::mma_sync(acc[i][j], fah[i], fbl[j], acc[i][j]);
                    wmma::mma_sync(acc[i][j], fal[i], fbh[j], acc[i][j]);
                }
        }
        __syncthreads();
    }
    #pragma unroll
    for (int i = 0; i < 2; i++)
        #pragma unroll
        for (int j = 0; j < 4; j++)
            wmma::store_matrix_sync(&d_C2[(size_t)(m0 + wm + i * 16) * 512 + n0 + wn + j * 16],
                                    acc[i][j], 512, wmma::mem_row_major);
}

// ---------------- finish kernels ----------------
__global__ void finish_h(const float* __restrict__ bias1) {
    int idx = blockIdx.x * blockDim.x + threadIdx.x;
    if (idx >= NNODES * 32) return;
    int row = idx >> 5, c4 = (idx & 31) << 2;
    float4 v = *(const float4*)&d_C1[(size_t)row * 128 + c4];
    v.x += bias1[c4]; v.y += bias1[c4 + 1]; v.z += bias1[c4 + 2]; v.w += bias1[c4 + 3];
    float vv[4] = { v.x, v.y, v.z, v.w };
    __align__(8) __nv_bfloat16 hi[4], lo[4];
    #pragma unroll
    for (int j = 0; j < 4; j++) split2(vv[j], hi[j], lo[j]);
    size_t b = (size_t)row * 128 + c4;
    *(uint2*)&d_hhi[b] = *(uint2*)hi;
    *(uint2*)&d_hlo[b] = *(uint2*)lo;
}

__global__ void finish_kqvs() {
    int idx = blockIdx.x * blockDim.x + threadIdx.x;
    if (idx >= NNODES * 128) return;
    int row = idx >> 7, c4 = (idx & 127) << 2;
    float4 v = *(const float4*)&d_C2[(size_t)row * 512 + c4];
    v.x += d_bcat[c4]; v.y += d_bcat[c4 + 1]; v.z += d_bcat[c4 + 2]; v.w += d_bcat[c4 + 3];
    int sel = c4 >> 7, cc = c4 & 127;
    float* dst;
    if (sel == 0)      dst = &d_kskip[(size_t)row * 256 + cc];
    else if (sel == 1) dst = &d_qv[(size_t)row * 256 + cc];
    else if (sel == 2) dst = &d_qv[(size_t)row * 256 + 128 + cc];
    else               dst = &d_kskip[(size_t)row * 256 + 128 + cc];
    *(float4*)dst = v;
}

// ---------------- gate ----------------
__global__ void gate_kernel(float* __restrict__ out) {
    int dst = blockIdx.x * 8 + (threadIdx.x >> 5);
    if (dst >= NNODES) return;
    int lane = threadIdx.x & 31;
    const float4* ks4 = reinterpret_cast<const float4*>(d_kskip);
    const float4* qv4 = reinterpret_cast<const float4*>(d_qv);
    float4 kd  = ks4[(size_t)dst * 64 + lane];
    float4 acc = ks4[(size_t)dst * 64 + 32 + lane];
    int beg = d_off[dst * NREL];
    int end = d_off[dst * NREL + NREL];
    for (int e = beg; e < end; e++) {
        int s = d_ssrc[e];
        float4 q = __ldg(&qv4[(size_t)s * 64 + lane]);
        float4 v = __ldg(&qv4[(size_t)s * 64 + 32 + lane]);
        acc.x += v.x * sigf(kd.x + q.x);
        acc.y += v.y * sigf(kd.y + q.y);
        acc.z += v.z * sigf(kd.z + q.z);
        acc.w += v.w * sigf(kd.w + q.w);
    }
    reinterpret_cast<float4*>(out)[(size_t)dst * 32 + lane] = acc;
}

// ---------------- launcher ----------------
extern "C" void kernel_launch(void* const* d_in, const int* in_sizes, int n_in,
                              void* d_out, int out_size) {
    const float* x     = (const float*)d_in[0];
    const int*   ei    = (const int*)  d_in[1];
    const int*   etype = (const int*)  d_in[3];
    const float* basis = (const float*)d_in[4];
    const float* comp  = (const float*)d_in[5];
    const float* root  = (const float*)d_in[6];
    const float* bias1 = (const float*)d_in[7];
    const float* wk = (const float*)d_in[8];  const float* bk = (const float*)d_in[9];
    const float* wq = (const float*)d_in[10]; const float* bq = (const float*)d_in[11];
    const float* wv = (const float*)d_in[12]; const float* bv = (const float*)d_in[13];
    const float* ws = (const float*)d_in[14]; const float* bs = (const float*)d_in[15];
    float* out = (float*)d_out;

    build_BT<<<(128 * NK + 255) / 256, 256>>>(comp, basis, root);
    pack_CT<<<(512 * 128 + 255) / 256, 256>>>(wk, bk, wq, bq, wv, bv, ws, bs);

    zero_cnt<<<(RN + 255) / 256, 256>>>();
    count_edges<<<(NEDGES + 255) / 256, 256>>>(ei, etype);
    scan_blocksum<<<NSCAN, SCAN_B>>>();
    scan_partials<<<1, SCAN_B>>>();
    scan_final<<<NSCAN, SCAN_B>>>();
    scatter_edges<<<(NEDGES + 255) / 256, 256>>>(ei, etype);

    xsplit<<<(NNODES * 32 + 255) / 256, 256>>>(x);
    agg_split<<<RN / 8, 256>>>(x);

    gemm1_wmma<<<MT, 256>>>();
    finish_h<<<(NNODES * 32 + 255) / 256, 256>>>(bias1);
    gemm2_wmma<<<dim3(MT, 4), 256>>>();
    finish_kqvs<<<(NNODES * 128 + 255) / 256, 256>>>();

    gate_kernel<<<(NNODES + 7) / 8, 256>>>(out);
}

// round 4
// speedup vs baseline: 1.5385x; 1.2292x over previous
#include <cuda_runtime.h>
#include <cuda_bf16.h>
#include <mma.h>
#include <cstdint>

using namespace nvcuda;

#define NNODES 50000
#define NEDGES 600000
#define NREL   8
#define NBASIS 32
#define RN     (NREL * NNODES)
#define SCAN_B 1024
#define NSCAN  ((RN + SCAN_B - 1) / SCAN_B)
#define NK     1152                      // GEMM1 K: 8*128 + 128 (root)
#define MT     ((NNODES + 127) / 128)    // 391 M-tiles

// ---------------- static device scratch ----------------
static __device__ __align__(16) __nv_bfloat16 d_Ahi[(size_t)NNODES * NK];
static __device__ __align__(16) __nv_bfloat16 d_Alo[(size_t)NNODES * NK];
static __device__ __align__(16) __nv_bfloat16 d_Bhi[128 * NK];   // [n][k]
static __device__ __align__(16) __nv_bfloat16 d_Blo[128 * NK];
static __device__ __align__(16) __nv_bfloat16 d_Chi[512 * 128];  // [n][k]
static __device__ __align__(16) __nv_bfloat16 d_Clo[512 * 128];
static __device__ __align__(16) float d_bcat[512];
static __device__ __align__(16) __nv_bfloat16 d_hhi[(size_t)NNODES * 128];
static __device__ __align__(16) __nv_bfloat16 d_hlo[(size_t)NNODES * 128];
static __device__ __align__(16) float d_kskip[(size_t)NNODES * 256]; // [k | skip]
static __device__ __align__(16) float d_qv[(size_t)NNODES * 256];    // [q | v]
static __device__ int d_cnt[RN];
static __device__ int d_off[RN + 1];
static __device__ int d_cur[RN];
static __device__ int d_ssrc[NEDGES];
static __device__ int d_part[SCAN_B];
static __device__ int d_ppre[SCAN_B];

// ---------------- helpers ----------------
__device__ __forceinline__ void split2(float v, __nv_bfloat16& hi, __nv_bfloat16& lo) {
    hi = __float2bfloat16(v);
    lo = __float2bfloat16(v - __bfloat162float(hi));
}
__device__ __forceinline__ float sigf(float z) { return 1.0f / (1.0f + __expf(-z)); }

// ---------------- weight prep ----------------
__global__ void build_BT(const float* __restrict__ comp, const float* __restrict__ basis,
                         const float* __restrict__ root) {
    int idx = blockIdx.x * blockDim.x + threadIdx.x;
    if (idx >= 128 * NK) return;
    int n = idx / NK, k = idx % NK;
    float w;
    if (k < 1024) {
        int r = k >> 7, i = k & 127;
        float s = 0.0f;
        #pragma unroll
        for (int b = 0; b < NBASIS; b++)
            s += comp[r * NBASIS + b] * basis[(b * 128 + i) * 128 + n];
        w = s;
    } else {
        w = root[(k - 1024) * 128 + n];
    }
    __nv_bfloat16 hi, lo; split2(w, hi, lo);
    d_Bhi[idx] = hi; d_Blo[idx] = lo;
}

__global__ void pack_CT(const float* wk, const float* bk, const float* wq, const float* bq,
                        const float* wv, const float* bv, const float* ws, const float* bs) {
    int idx = blockIdx.x * blockDim.x + threadIdx.x;
    if (idx >= 512 * 128) return;
    int n = idx >> 7, k = idx & 127;
    int sel = n >> 7, cc = n & 127;
    const float* W = (sel == 0) ? wk : (sel == 1) ? wq : (sel == 2) ? wv : ws;
    __nv_bfloat16 hi, lo; split2(W[k * 128 + cc], hi, lo);
    d_Chi[idx] = hi; d_Clo[idx] = lo;
    if (k == 0) {
        const float* B = (sel == 0) ? bk : (sel == 1) ? bq : (sel == 2) ? bv : bs;
        d_bcat[n] = B[cc];
    }
}

// ---------------- CSR build ----------------
__global__ void zero_cnt() {
    int i = blockIdx.x * blockDim.x + threadIdx.x;
    if (i < RN) d_cnt[i] = 0;
}
__global__ void count_edges(const int* __restrict__ ei, const int* __restrict__ etype) {
    int e = blockIdx.x * blockDim.x + threadIdx.x;
    if (e >= NEDGES) return;
    atomicAdd(&d_cnt[ei[NEDGES + e] * NREL + etype[e]], 1);
}
__global__ void scan_blocksum() {
    __shared__ int s[SCAN_B];
    int tid = threadIdx.x, gid = blockIdx.x * SCAN_B + tid;
    s[tid] = (gid < RN) ? d_cnt[gid] : 0;
    __syncthreads();
    for (int o = SCAN_B / 2; o > 0; o >>= 1) { if (tid < o) s[tid] += s[tid + o]; __syncthreads(); }
    if (tid == 0) d_part[blockIdx.x] = s[0];
}
__global__ void scan_partials() {
    __shared__ int s[SCAN_B];
    int tid = threadIdx.x;
    int v = (tid < NSCAN) ? d_part[tid] : 0;
    s[tid] = v; __syncthreads();
    for (int o = 1; o < SCAN_B; o <<= 1) {
        int t = (tid >= o) ? s[tid - o] : 0; __syncthreads();
        s[tid] += t; __syncthreads();
    }
    d_ppre[tid] = s[tid] - v;
}
__global__ void scan_final() {
    __shared__ int s[SCAN_B];
    int tid = threadIdx.x, gid = blockIdx.x * SCAN_B + tid;
    int v = (gid < RN) ? d_cnt[gid] : 0;
    s[tid] = v; __syncthreads();
    for (int o = 1; o < SCAN_B; o <<= 1) {
        int t = (tid >= o) ? s[tid - o] : 0; __syncthreads();
        s[tid] += t; __syncthreads();
    }
    int ex = s[tid] - v + d_ppre[blockIdx.x];
    if (gid < RN) {
        d_off[gid] = ex; d_cur[gid] = ex;
        if (gid == RN - 1) d_off[RN] = ex + v;
    }
}
__global__ void scatter_edges(const int* __restrict__ ei, const int* __restrict__ etype) {
    int e = blockIdx.x * blockDim.x + threadIdx.x;
    if (e >= NEDGES) return;
    int pos = atomicAdd(&d_cur[ei[NEDGES + e] * NREL + etype[e]], 1);
    d_ssrc[pos] = ei[e];
}

// ---------------- gather: per-(dst,rel) mean -> split-bf16 A cols 0..1023 ----------------
__global__ void agg_split(const float* __restrict__ x) {
    int seg = blockIdx.x * 8 + (threadIdx.x >> 5);
    if (seg >= RN) return;
    int lane = threadIdx.x & 31;
    int beg = d_off[seg], end = d_off[seg + 1];
    int dst = seg >> 3, r = seg & 7;
    const float4* x4 = reinterpret_cast<const float4*>(x);
    float4 acc = make_float4(0.f, 0.f, 0.f, 0.f);
    for (int e = beg; e < end; e++) {
        float4 v = __ldg(&x4[(size_t)d_ssrc[e] * 32 + lane]);
        acc.x += v.x; acc.y += v.y; acc.z += v.z; acc.w += v.w;
    }
    float inv = (end > beg) ? 1.0f / (float)(end - beg) : 0.0f;
    float vv[4] = { acc.x * inv, acc.y * inv, acc.z * inv, acc.w * inv };
    __align__(8) __nv_bfloat16 hi[4], lo[4];
    #pragma unroll
    for (int j = 0; j < 4; j++) split2(vv[j], hi[j], lo[j]);
    size_t b = (size_t)dst * NK + r * 128 + lane * 4;
    *(uint2*)&d_Ahi[b] = *(uint2*)hi;
    *(uint2*)&d_Alo[b] = *(uint2*)lo;
}

// x -> split-bf16 A cols 1024..1151 (root term)
__global__ void xsplit(const float* __restrict__ x) {
    int idx = blockIdx.x * blockDim.x + threadIdx.x;
    if (idx >= NNODES * 32) return;
    int row = idx >> 5, l = idx & 31;
    float4 v = reinterpret_cast<const float4*>(x)[(size_t)row * 32 + l];
    float vv[4] = { v.x, v.y, v.z, v.w };
    __align__(8) __nv_bfloat16 hi[4], lo[4];
    #pragma unroll
    for (int j = 0; j < 4; j++) split2(vv[j], hi[j], lo[j]);
    size_t b = (size_t)row * NK + 1024 + l * 4;
    *(uint2*)&d_Ahi[b] = *(uint2*)hi;
    *(uint2*)&d_Alo[b] = *(uint2*)lo;
}

// ---------------- wmma GEMMs (3-product bf16 split, fused epilogues) ----------------
typedef wmma::fragment<wmma::matrix_a, 16, 16, 16, __nv_bfloat16, wmma::row_major> FragA;
typedef wmma::fragment<wmma::matrix_b, 16, 16, 16, __nv_bfloat16, wmma::col_major> FragB;
typedef wmma::fragment<wmma::accumulator, 16, 16, 16, float> FragC;

// dynamic smem: stage tiles (4 x 128 x 40 bf16 = 40,960 B) unioned with
// epilogue buffer (128 x 132 fp32 = 67,584 B)
#define GSMEM 67584
#define SA_H(p) ((__nv_bfloat16*)(p))
#define SA_L(p) ((__nv_bfloat16*)(p) + 5120)
#define SB_H(p) ((__nv_bfloat16*)(p) + 10240)
#define SB_L(p) ((__nv_bfloat16*)(p) + 15360)

__global__ void __launch_bounds__(256, 2) gemm1_wmma(const float* __restrict__ bias1) {
    extern __shared__ __align__(16) char sm[];
    int tid = threadIdx.x, wid = tid >> 5;
    int m0 = blockIdx.x << 7;
    int wm = (wid & 3) << 5;
    int wn = (wid >> 2) << 6;

    FragC acc[2][4];
    #pragma unroll
    for (int i = 0; i < 2; i++)
        #pragma unroll
        for (int j = 0; j < 4; j++) wmma::fill_fragment(acc[i][j], 0.0f);

    for (int ch = 0; ch < NK / 32; ch++) {
        int k0 = ch << 5;
        #pragma unroll
        for (int t = tid; t < 512; t += 256) {
            int row = t >> 2, c8 = (t & 3) << 3;
            int gr = m0 + row;
            uint4 vh = make_uint4(0, 0, 0, 0), vl = make_uint4(0, 0, 0, 0);
            if (gr < NNODES) {
                size_t ga = (size_t)gr * NK + k0 + c8;
                vh = *(const uint4*)(d_Ahi + ga);
                vl = *(const uint4*)(d_Alo + ga);
            }
            *(uint4*)&SA_H(sm)[row * 40 + c8] = vh;
            *(uint4*)&SA_L(sm)[row * 40 + c8] = vl;
            size_t gb = (size_t)row * NK + k0 + c8;
            *(uint4*)&SB_H(sm)[row * 40 + c8] = *(const uint4*)(d_Bhi + gb);
            *(uint4*)&SB_L(sm)[row * 40 + c8] = *(const uint4*)(d_Blo + gb);
        }
        __syncthreads();
        #pragma unroll
        for (int kk = 0; kk < 32; kk += 16) {
            FragA fah[2], fal[2];
            #pragma unroll
            for (int i = 0; i < 2; i++) {
                wmma::load_matrix_sync(fah[i], &SA_H(sm)[(wm + i * 16) * 40 + kk], 40);
                wmma::load_matrix_sync(fal[i], &SA_L(sm)[(wm + i * 16) * 40 + kk], 40);
            }
            #pragma unroll
            for (int j = 0; j < 4; j++) {
                FragB fbh, fbl;
                wmma::load_matrix_sync(fbh, &SB_H(sm)[(wn + j * 16) * 40 + kk], 40);
                wmma::load_matrix_sync(fbl, &SB_L(sm)[(wn + j * 16) * 40 + kk], 40);
                #pragma unroll
                for (int i = 0; i < 2; i++) {
                    wmma::mma_sync(acc[i][j], fah[i], fbh, acc[i][j]);
                    wmma::mma_sync(acc[i][j], fah[i], fbl, acc[i][j]);
                    wmma::mma_sync(acc[i][j], fal[i], fbh, acc[i][j]);
                }
            }
        }
        __syncthreads();
    }

    // fused epilogue: frags -> smem -> bias + split-bf16 h
    float* sC = (float*)sm;
    #pragma unroll
    for (int i = 0; i < 2; i++)
        #pragma unroll
        for (int j = 0; j < 4; j++)
            wmma::store_matrix_sync(&sC[(wm + i * 16) * 132 + wn + j * 16],
                                    acc[i][j], 132, wmma::mem_row_major);
    __syncthreads();
    for (int t = tid; t < 4096; t += 256) {
        int row = t >> 5, c4 = (t & 31) << 2;
        int gr = m0 + row;
        if (gr >= NNODES) continue;
        const float* p = &sC[row * 132 + c4];
        float vv[4] = { p[0] + bias1[c4], p[1] + bias1[c4 + 1],
                        p[2] + bias1[c4 + 2], p[3] + bias1[c4 + 3] };
        __align__(8) __nv_bfloat16 hi[4], lo[4];
        #pragma unroll
        for (int j = 0; j < 4; j++) split2(vv[j], hi[j], lo[j]);
        size_t b = (size_t)gr * 128 + c4;
        *(uint2*)&d_hhi[b] = *(uint2*)hi;
        *(uint2*)&d_hlo[b] = *(uint2*)lo;
    }
}

__global__ void __launch_bounds__(256, 2) gemm2_wmma() {
    extern __shared__ __align__(16) char sm[];
    int tid = threadIdx.x, wid = tid >> 5;
    int m0 = blockIdx.x << 7;
    int n0 = blockIdx.y << 7;
    int wm = (wid & 3) << 5;
    int wn = (wid >> 2) << 6;

    FragC acc[2][4];
    #pragma unroll
    for (int i = 0; i < 2; i++)
        #pragma unroll
        for (int j = 0; j < 4; j++) wmma::fill_fragment(acc[i][j], 0.0f);

    for (int ch = 0; ch < 4; ch++) {
        int k0 = ch << 5;
        #pragma unroll
        for (int t = tid; t < 512; t += 256) {
            int row = t >> 2, c8 = (t & 3) << 3;
            int gr = m0 + row;
            uint4 vh = make_uint4(0, 0, 0, 0), vl = make_uint4(0, 0, 0, 0);
            if (gr < NNODES) {
                size_t ga = (size_t)gr * 128 + k0 + c8;
                vh = *(const uint4*)(d_hhi + ga);
                vl = *(const uint4*)(d_hlo + ga);
            }
            *(uint4*)&SA_H(sm)[row * 40 + c8] = vh;
            *(uint4*)&SA_L(sm)[row * 40 + c8] = vl;
            size_t gb = (size_t)(n0 + row) * 128 + k0 + c8;
            *(uint4*)&SB_H(sm)[row * 40 + c8] = *(const uint4*)(d_Chi + gb);
            *(uint4*)&SB_L(sm)[row * 40 + c8] = *(const uint4*)(d_Clo + gb);
        }
        __syncthreads();
        #pragma unroll
        for (int kk = 0; kk < 32; kk += 16) {
            FragA fah[2], fal[2];
            #pragma unroll
            for (int i = 0; i < 2; i++) {
                wmma::load_matrix_sync(fah[i], &SA_H(sm)[(wm + i * 16) * 40 + kk], 40);
                wmma::load_matrix_sync(fal[i], &SA_L(sm)[(wm + i * 16) * 40 + kk], 40);
            }
            #pragma unroll
            for (int j = 0; j < 4; j++) {
                FragB fbh, fbl;
                wmma::load_matrix_sync(fbh, &SB_H(sm)[(wn + j * 16) * 40 + kk], 40);
                wmma::load_matrix_sync(fbl, &SB_L(sm)[(wn + j * 16) * 40 + kk], 40);
                #pragma unroll
                for (int i = 0; i < 2; i++) {
                    wmma::mma_sync(acc[i][j], fah[i], fbh, acc[i][j]);
                    wmma::mma_sync(acc[i][j], fah[i], fbl, acc[i][j]);
                    wmma::mma_sync(acc[i][j], fal[i], fbh, acc[i][j]);
                }
            }
        }
        __syncthreads();
    }

    // fused epilogue: frags -> smem -> +bcat -> scatter into kskip / qv
    float* sC = (float*)sm;
    #pragma unroll
    for (int i = 0; i < 2; i++)
        #pragma unroll
        for (int j = 0; j < 4; j++)
            wmma::store_matrix_sync(&sC[(wm + i * 16) * 132 + wn + j * 16],
                                    acc[i][j], 132, wmma::mem_row_major);
    __syncthreads();
    int sel = n0 >> 7;   // 0:k, 1:q, 2:v, 3:skip
    for (int t = tid; t < 4096; t += 256) {
        int row = t >> 5, c4 = (t & 31) << 2;
        int gr = m0 + row;
        if (gr >= NNODES) continue;
        const float* p = &sC[row * 132 + c4];
        int c = n0 + c4;
        float4 v = make_float4(p[0] + d_bcat[c], p[1] + d_bcat[c + 1],
                               p[2] + d_bcat[c + 2], p[3] + d_bcat[c + 3]);
        float* dst;
        if (sel == 0)      dst = &d_kskip[(size_t)gr * 256 + c4];
        else if (sel == 1) dst = &d_qv[(size_t)gr * 256 + c4];
        else if (sel == 2) dst = &d_qv[(size_t)gr * 256 + 128 + c4];
        else               dst = &d_kskip[(size_t)gr * 256 + 128 + c4];
        *(float4*)dst = v;
    }
}

// ---------------- gate ----------------
__global__ void gate_kernel(float* __restrict__ out) {
    int dst = blockIdx.x * 8 + (threadIdx.x >> 5);
    if (dst >= NNODES) return;
    int lane = threadIdx.x & 31;
    const float4* ks4 = reinterpret_cast<const float4*>(d_kskip);
    const float4* qv4 = reinterpret_cast<const float4*>(d_qv);
    float4 kd  = ks4[(size_t)dst * 64 + lane];
    float4 acc = ks4[(size_t)dst * 64 + 32 + lane];
    int beg = d_off[dst * NREL];
    int end = d_off[dst * NREL + NREL];
    for (int e = beg; e < end; e++) {
        int s = d_ssrc[e];
        float4 q = __ldg(&qv4[(size_t)s * 64 + lane]);
        float4 v = __ldg(&qv4[(size_t)s * 64 + 32 + lane]);
        acc.x += v.x * sigf(kd.x + q.x);
        acc.y += v.y * sigf(kd.y + q.y);
        acc.z += v.z * sigf(kd.z + q.z);
        acc.w += v.w * sigf(kd.w + q.w);
    }
    reinterpret_cast<float4*>(out)[(size_t)dst * 32 + lane] = acc;
}

// ---------------- launcher ----------------
extern "C" void kernel_launch(void* const* d_in, const int* in_sizes, int n_in,
                              void* d_out, int out_size) {
    const float* x     = (const float*)d_in[0];
    const int*   ei    = (const int*)  d_in[1];
    const int*   etype = (const int*)  d_in[3];
    const float* basis = (const float*)d_in[4];
    const float* comp  = (const float*)d_in[5];
    const float* root  = (const float*)d_in[6];
    const float* bias1 = (const float*)d_in[7];
    const float* wk = (const float*)d_in[8];  const float* bk = (const float*)d_in[9];
    const float* wq = (const float*)d_in[10]; const float* bq = (const float*)d_in[11];
    const float* wv = (const float*)d_in[12]; const float* bv = (const float*)d_in[13];
    const float* ws = (const float*)d_in[14]; const float* bs = (const float*)d_in[15];
    float* out = (float*)d_out;

    cudaFuncSetAttribute(gemm1_wmma, cudaFuncAttributeMaxDynamicSharedMemorySize, GSMEM);
    cudaFuncSetAttribute(gemm2_wmma, cudaFuncAttributeMaxDynamicSharedMemorySize, GSMEM);

    build_BT<<<(128 * NK + 255) / 256, 256>>>(comp, basis, root);
    pack_CT<<<(512 * 128 + 255) / 256, 256>>>(wk, bk, wq, bq, wv, bv, ws, bs);

    zero_cnt<<<(RN + 255) / 256, 256>>>();
    count_edges<<<(NEDGES + 255) / 256, 256>>>(ei, etype);
    scan_blocksum<<<NSCAN, SCAN_B>>>();
    scan_partials<<<1, SCAN_B>>>();
    scan_final<<<NSCAN, SCAN_B>>>();
    scatter_edges<<<(NEDGES + 255) / 256, 256>>>(ei, etype);

    xsplit<<<(NNODES * 32 + 255) / 256, 256>>>(x);
    agg_split<<<RN / 8, 256>>>(x);

    gemm1_wmma<<<MT, 256, GSMEM>>>(bias1);
    gemm2_wmma<<<dim3(MT, 4), 256, GSMEM>>>();

    gate_kernel<<<(NNODES + 7) / 8, 256>>>(out);
}

// round 5
// speedup vs baseline: 1.7109x; 1.1121x over previous
#include <cuda_runtime.h>
#include <cuda_bf16.h>
#include <mma.h>
#include <cstdint>

using namespace nvcuda;

#define NNODES 50000
#define NEDGES 600000
#define NREL   8
#define NBASIS 32
#define RN     (NREL * NNODES)
#define SCAN_B 1024
#define NSCAN  ((RN + SCAN_B - 1) / SCAN_B)
#define NK     1152
#define MT     ((NNODES + 127) / 128)

// ---------------- static device scratch ----------------
static __device__ __align__(16) __nv_bfloat16 d_Ahi[(size_t)NNODES * NK];
static __device__ __align__(16) __nv_bfloat16 d_Alo[(size_t)NNODES * NK];
static __device__ __align__(16) __nv_bfloat16 d_Bhi[128 * NK];
static __device__ __align__(16) __nv_bfloat16 d_Blo[128 * NK];
static __device__ __align__(16) __nv_bfloat16 d_Chi[512 * 128];
static __device__ __align__(16) __nv_bfloat16 d_Clo[512 * 128];
static __device__ __align__(16) float d_bcat[512];
static __device__ __align__(16) __nv_bfloat16 d_hhi[(size_t)NNODES * 128];
static __device__ __align__(16) __nv_bfloat16 d_hlo[(size_t)NNODES * 128];
static __device__ __align__(16) float d_kskip[(size_t)NNODES * 256];
static __device__ __align__(16) float d_qv[(size_t)NNODES * 256];
static __device__ int d_cnt[RN];
static __device__ int d_off[RN + 1];
static __device__ int d_cur[RN];
static __device__ int d_ssrc[NEDGES];
static __device__ int d_part[SCAN_B];
static __device__ int d_ppre[SCAN_B];

// ---------------- helpers ----------------
__device__ __forceinline__ void split2(float v, __nv_bfloat16& hi, __nv_bfloat16& lo) {
    hi = __float2bfloat16(v);
    lo = __float2bfloat16(v - __bfloat162float(hi));
}
__device__ __forceinline__ float sigf(float z) { return 1.0f / (1.0f + __expf(-z)); }
__device__ __forceinline__ uint32_t smem_u32(const void* p) {
    uint32_t a;
    asm("{ .reg .u64 t; cvta.to.shared.u64 t, %1; cvt.u32.u64 %0, t; }" : "=r"(a) : "l"(p));
    return a;
}
__device__ __forceinline__ void cpa(uint32_t d, const void* s, int srcsz) {
    asm volatile("cp.async.cg.shared.global [%0], [%1], 16, %2;"
                 :: "r"(d), "l"(s), "r"(srcsz) : "memory");
}
#define CP_COMMIT() asm volatile("cp.async.commit_group;" ::: "memory")
#define CP_WAIT1()  asm volatile("cp.async.wait_group 1;" ::: "memory")
#define CP_WAIT0()  asm volatile("cp.async.wait_group 0;" ::: "memory")

// ---------------- weight prep ----------------
__global__ void build_BT(const float* __restrict__ comp, const float* __restrict__ basis,
                         const float* __restrict__ root) {
    int idx = blockIdx.x * blockDim.x + threadIdx.x;
    if (idx >= 128 * NK) return;
    int n = idx / NK, k = idx % NK;
    float w;
    if (k < 1024) {
        int r = k >> 7, i = k & 127;
        float s = 0.0f;
        #pragma unroll
        for (int b = 0; b < NBASIS; b++)
            s += comp[r * NBASIS + b] * basis[(b * 128 + i) * 128 + n];
        w = s;
    } else {
        w = root[(k - 1024) * 128 + n];
    }
    __nv_bfloat16 hi, lo; split2(w, hi, lo);
    d_Bhi[idx] = hi; d_Blo[idx] = lo;
}

__global__ void pack_CT(const float* wk, const float* bk, const float* wq, const float* bq,
                        const float* wv, const float* bv, const float* ws, const float* bs) {
    int idx = blockIdx.x * blockDim.x + threadIdx.x;
    if (idx >= 512 * 128) return;
    int n = idx >> 7, k = idx & 127;
    int sel = n >> 7, cc = n & 127;
    const float* W = (sel == 0) ? wk : (sel == 1) ? wq : (sel == 2) ? wv : ws;
    __nv_bfloat16 hi, lo; split2(W[k * 128 + cc], hi, lo);
    d_Chi[idx] = hi; d_Clo[idx] = lo;
    if (k == 0) {
        const float* B = (sel == 0) ? bk : (sel == 1) ? bq : (sel == 2) ? bv : bs;
        d_bcat[n] = B[cc];
    }
}

// ---------------- CSR build ----------------
__global__ void zero_cnt() {
    int i = blockIdx.x * blockDim.x + threadIdx.x;
    if (i < RN) d_cnt[i] = 0;
}
__global__ void count_edges(const int* __restrict__ ei, const int* __restrict__ etype) {
    int e = blockIdx.x * blockDim.x + threadIdx.x;
    if (e >= NEDGES) return;
    atomicAdd(&d_cnt[ei[NEDGES + e] * NREL + etype[e]], 1);
}
__global__ void scan_blocksum() {
    __shared__ int s[SCAN_B];
    int tid = threadIdx.x, gid = blockIdx.x * SCAN_B + tid;
    s[tid] = (gid < RN) ? d_cnt[gid] : 0;
    __syncthreads();
    for (int o = SCAN_B / 2; o > 0; o >>= 1) { if (tid < o) s[tid] += s[tid + o]; __syncthreads(); }
    if (tid == 0) d_part[blockIdx.x] = s[0];
}
__global__ void scan_partials() {
    __shared__ int s[SCAN_B];
    int tid = threadIdx.x;
    int v = (tid < NSCAN) ? d_part[tid] : 0;
    s[tid] = v; __syncthreads();
    for (int o = 1; o < SCAN_B; o <<= 1) {
        int t = (tid >= o) ? s[tid - o] : 0; __syncthreads();
        s[tid] += t; __syncthreads();
    }
    d_ppre[tid] = s[tid] - v;
}
__global__ void scan_final() {
    __shared__ int s[SCAN_B];
    int tid = threadIdx.x, gid = blockIdx.x * SCAN_B + tid;
    int v = (gid < RN) ? d_cnt[gid] : 0;
    s[tid] = v; __syncthreads();
    for (int o = 1; o < SCAN_B; o <<= 1) {
        int t = (tid >= o) ? s[tid - o] : 0; __syncthreads();
        s[tid] += t; __syncthreads();
    }
    int ex = s[tid] - v + d_ppre[blockIdx.x];
    if (gid < RN) {
        d_off[gid] = ex; d_cur[gid] = ex;
        if (gid == RN - 1) d_off[RN] = ex + v;
    }
}
__global__ void scatter_edges(const int* __restrict__ ei, const int* __restrict__ etype) {
    int e = blockIdx.x * blockDim.x + threadIdx.x;
    if (e >= NEDGES) return;
    int pos = atomicAdd(&d_cur[ei[NEDGES + e] * NREL + etype[e]], 1);
    d_ssrc[pos] = ei[e];
}

// ---------------- gather ----------------
__global__ void agg_split(const float* __restrict__ x) {
    int seg = blockIdx.x * 8 + (threadIdx.x >> 5);
    if (seg >= RN) return;
    int lane = threadIdx.x & 31;
    int beg = d_off[seg], end = d_off[seg + 1];
    int dst = seg >> 3, r = seg & 7;
    const float4* x4 = reinterpret_cast<const float4*>(x);
    float4 acc = make_float4(0.f, 0.f, 0.f, 0.f);
    for (int e = beg; e < end; e++) {
        float4 v = __ldg(&x4[(size_t)d_ssrc[e] * 32 + lane]);
        acc.x += v.x; acc.y += v.y; acc.z += v.z; acc.w += v.w;
    }
    float inv = (end > beg) ? 1.0f / (float)(end - beg) : 0.0f;
    float vv[4] = { acc.x * inv, acc.y * inv, acc.z * inv, acc.w * inv };
    __align__(8) __nv_bfloat16 hi[4], lo[4];
    #pragma unroll
    for (int j = 0; j < 4; j++) split2(vv[j], hi[j], lo[j]);
    size_t b = (size_t)dst * NK + r * 128 + lane * 4;
    *(uint2*)&d_Ahi[b] = *(uint2*)hi;
    *(uint2*)&d_Alo[b] = *(uint2*)lo;
}

__global__ void xsplit(const float* __restrict__ x) {
    int idx = blockIdx.x * blockDim.x + threadIdx.x;
    if (idx >= NNODES * 32) return;
    int row = idx >> 5, l = idx & 31;
    float4 v = reinterpret_cast<const float4*>(x)[(size_t)row * 32 + l];
    float vv[4] = { v.x, v.y, v.z, v.w };
    __align__(8) __nv_bfloat16 hi[4], lo[4];
    #pragma unroll
    for (int j = 0; j < 4; j++) split2(vv[j], hi[j], lo[j]);
    size_t b = (size_t)row * NK + 1024 + l * 4;
    *(uint2*)&d_Ahi[b] = *(uint2*)hi;
    *(uint2*)&d_Alo[b] = *(uint2*)lo;
}

// ---------------- wmma GEMMs with cp.async 2-stage pipeline ----------------
typedef wmma::fragment<wmma::matrix_a, 16, 16, 16, __nv_bfloat16, wmma::row_major> FragA;
typedef wmma::fragment<wmma::matrix_b, 16, 16, 16, __nv_bfloat16, wmma::col_major> FragB;
typedef wmma::fragment<wmma::accumulator, 16, 16, 16, float> FragC;

// stage layout (bf16 elements): A_hi[128*40] | A_lo | B_hi | B_lo ; stage = 40960 B
#define STAGE_B 40960
#define GSMEM   (2 * STAGE_B)    // 81920 B (epilogue fp32 buf 67584 B fits inside)

__device__ __forceinline__ void mma_block(char* sm, int st, int wm, int wn, FragC acc[2][4]) {
    __nv_bfloat16* p = (__nv_bfloat16*)(sm + st * STAGE_B);
    #pragma unroll
    for (int kk = 0; kk < 32; kk += 16) {
        FragA fah[2], fal[2];
        #pragma unroll
        for (int i = 0; i < 2; i++) {
            wmma::load_matrix_sync(fah[i], p + (wm + i * 16) * 40 + kk, 40);
            wmma::load_matrix_sync(fal[i], p + 5120 + (wm + i * 16) * 40 + kk, 40);
        }
        #pragma unroll
        for (int j = 0; j < 4; j++) {
            FragB fbh, fbl;
            wmma::load_matrix_sync(fbh, p + 10240 + (wn + j * 16) * 40 + kk, 40);
            wmma::load_matrix_sync(fbl, p + 15360 + (wn + j * 16) * 40 + kk, 40);
            #pragma unroll
            for (int i = 0; i < 2; i++) {
                wmma::mma_sync(acc[i][j], fah[i], fbh, acc[i][j]);
                wmma::mma_sync(acc[i][j], fah[i], fbl, acc[i][j]);
                wmma::mma_sync(acc[i][j], fal[i], fbh, acc[i][j]);
            }
        }
    }
}

__global__ void __launch_bounds__(256, 2) gemm1_wmma(const float* __restrict__ bias1) {
    extern __shared__ __align__(16) char sm[];
    uint32_t sa = smem_u32(sm);
    int tid = threadIdx.x, wid = tid >> 5;
    int m0 = blockIdx.x << 7;
    int wm = (wid & 3) << 5;
    int wn = (wid >> 2) << 6;

    FragC acc[2][4];
    #pragma unroll
    for (int i = 0; i < 2; i++)
        #pragma unroll
        for (int j = 0; j < 4; j++) wmma::fill_fragment(acc[i][j], 0.0f);

    // issue async loads for chunk ch into stage st
    auto issue = [&](int ch, int st) {
        int k0 = ch << 5;
        uint32_t so = sa + st * STAGE_B;
        #pragma unroll
        for (int t = tid; t < 512; t += 256) {
            int row = t >> 2, c8 = (t & 3) << 3;
            int gr = m0 + row;
            int pr = (gr < NNODES) ? 16 : 0;
            int grc = (gr < NNODES) ? gr : 0;
            size_t ga = (size_t)grc * NK + k0 + c8;
            uint32_t ds = so + row * 80 + c8 * 2;
            cpa(ds,         d_Ahi + ga, pr);
            cpa(ds + 10240, d_Alo + ga, pr);
            size_t gb = (size_t)row * NK + k0 + c8;
            cpa(ds + 20480, d_Bhi + gb, 16);
            cpa(ds + 30720, d_Blo + gb, 16);
        }
    };

    issue(0, 0);
    CP_COMMIT();
    const int NCH = NK / 32;   // 36
    for (int ch = 0; ch < NCH; ch++) {
        if (ch + 1 < NCH) issue(ch + 1, (ch + 1) & 1);
        CP_COMMIT();
        CP_WAIT1();
        __syncthreads();
        mma_block(sm, ch & 1, wm, wn, acc);
        __syncthreads();
    }
    CP_WAIT0();

    // fused epilogue
    float* sC = (float*)sm;
    #pragma unroll
    for (int i = 0; i < 2; i++)
        #pragma unroll
        for (int j = 0; j < 4; j++)
            wmma::store_matrix_sync(&sC[(wm + i * 16) * 132 + wn + j * 16],
                                    acc[i][j], 132, wmma::mem_row_major);
    __syncthreads();
    for (int t = tid; t < 4096; t += 256) {
        int row = t >> 5, c4 = (t & 31) << 2;
        int gr = m0 + row;
        if (gr >= NNODES) continue;
        const float* p = &sC[row * 132 + c4];
        float vv[4] = { p[0] + bias1[c4], p[1] + bias1[c4 + 1],
                        p[2] + bias1[c4 + 2], p[3] + bias1[c4 + 3] };
        __align__(8) __nv_bfloat16 hi[4], lo[4];
        #pragma unroll
        for (int j = 0; j < 4; j++) split2(vv[j], hi[j], lo[j]);
        size_t b = (size_t)gr * 128 + c4;
        *(uint2*)&d_hhi[b] = *(uint2*)hi;
        *(uint2*)&d_hlo[b] = *(uint2*)lo;
    }
}

__global__ void __launch_bounds__(256, 2) gemm2_wmma() {
    extern __shared__ __align__(16) char sm[];
    uint32_t sa = smem_u32(sm);
    int tid = threadIdx.x, wid = tid >> 5;
    int m0 = blockIdx.x << 7;
    int n0 = blockIdx.y << 7;
    int wm = (wid & 3) << 5;
    int wn = (wid >> 2) << 6;

    FragC acc[2][4];
    #pragma unroll
    for (int i = 0; i < 2; i++)
        #pragma unroll
        for (int j = 0; j < 4; j++) wmma::fill_fragment(acc[i][j], 0.0f);

    auto issue = [&](int ch, int st) {
        int k0 = ch << 5;
        uint32_t so = sa + st * STAGE_B;
        #pragma unroll
        for (int t = tid; t < 512; t += 256) {
            int row = t >> 2, c8 = (t & 3) << 3;
            int gr = m0 + row;
            int pr = (gr < NNODES) ? 16 : 0;
            int grc = (gr < NNODES) ? gr : 0;
            size_t ga = (size_t)grc * 128 + k0 + c8;
            uint32_t ds = so + row * 80 + c8 * 2;
            cpa(ds,         d_hhi + ga, pr);
            cpa(ds + 10240, d_hlo + ga, pr);
            size_t gb = (size_t)(n0 + row) * 128 + k0 + c8;
            cpa(ds + 20480, d_Chi + gb, 16);
            cpa(ds + 30720, d_Clo + gb, 16);
        }
    };

    issue(0, 0);
    CP_COMMIT();
    for (int ch = 0; ch < 4; ch++) {
        if (ch + 1 < 4) issue(ch + 1, (ch + 1) & 1);
        CP_COMMIT();
        CP_WAIT1();
        __syncthreads();
        mma_block(sm, ch & 1, wm, wn, acc);
        __syncthreads();
    }
    CP_WAIT0();

    float* sC = (float*)sm;
    #pragma unroll
    for (int i = 0; i < 2; i++)
        #pragma unroll
        for (int j = 0; j < 4; j++)
            wmma::store_matrix_sync(&sC[(wm + i * 16) * 132 + wn + j * 16],
                                    acc[i][j], 132, wmma::mem_row_major);
    __syncthreads();
    int sel = n0 >> 7;
    for (int t = tid; t < 4096; t += 256) {
        int row = t >> 5, c4 = (t & 31) << 2;
        int gr = m0 + row;
        if (gr >= NNODES) continue;
        const float* p = &sC[row * 132 + c4];
        int c = n0 + c4;
        float4 v = make_float4(p[0] + d_bcat[c], p[1] + d_bcat[c + 1],
                               p[2] + d_bcat[c + 2], p[3] + d_bcat[c + 3]);
        float* dst;
        if (sel == 0)      dst = &d_kskip[(size_t)gr * 256 + c4];
        else if (sel == 1) dst = &d_qv[(size_t)gr * 256 + c4];
        else if (sel == 2) dst = &d_qv[(size_t)gr * 256 + 128 + c4];
        else               dst = &d_kskip[(size_t)gr * 256 + 128 + c4];
        *(float4*)dst = v;
    }
}

// ---------------- gate ----------------
__global__ void gate_kernel(float* __restrict__ out) {
    int dst = blockIdx.x * 8 + (threadIdx.x >> 5);
    if (dst >= NNODES) return;
    int lane = threadIdx.x & 31;
    const float4* ks4 = reinterpret_cast<const float4*>(d_kskip);
    const float4* qv4 = reinterpret_cast<const float4*>(d_qv);
    float4 kd  = ks4[(size_t)dst * 64 + lane];
    float4 acc = ks4[(size_t)dst * 64 + 32 + lane];
    int beg = d_off[dst * NREL];
    int end = d_off[dst * NREL + NREL];
    for (int e = beg; e < end; e++) {
        int s = d_ssrc[e];
        float4 q = __ldg(&qv4[(size_t)s * 64 + lane]);
        float4 v = __ldg(&qv4[(size_t)s * 64 + 32 + lane]);
        acc.x += v.x * sigf(kd.x + q.x);
        acc.y += v.y * sigf(kd.y + q.y);
        acc.z += v.z * sigf(kd.z + q.z);
        acc.w += v.w * sigf(kd.w + q.w);
    }
    reinterpret_cast<float4*>(out)[(size_t)dst * 32 + lane] = acc;
}

// ---------------- launcher ----------------
extern "C" void kernel_launch(void* const* d_in, const int* in_sizes, int n_in,
                              void* d_out, int out_size) {
    const float* x     = (const float*)d_in[0];
    const int*   ei    = (const int*)  d_in[1];
    const int*   etype = (const int*)  d_in[3];
    const float* basis = (const float*)d_in[4];
    const float* comp  = (const float*)d_in[5];
    const float* root  = (const float*)d_in[6];
    const float* bias1 = (const float*)d_in[7];
    const float* wk = (const float*)d_in[8];  const float* bk = (const float*)d_in[9];
    const float* wq = (const float*)d_in[10]; const float* bq = (const float*)d_in[11];
    const float* wv = (const float*)d_in[12]; const float* bv = (const float*)d_in[13];
    const float* ws = (const float*)d_in[14]; const float* bs = (const float*)d_in[15];
    float* out = (float*)d_out;

    cudaFuncSetAttribute(gemm1_wmma, cudaFuncAttributeMaxDynamicSharedMemorySize, GSMEM);
    cudaFuncSetAttribute(gemm2_wmma, cudaFuncAttributeMaxDynamicSharedMemorySize, GSMEM);

    build_BT<<<(128 * NK + 255) / 256, 256>>>(comp, basis, root);
    pack_CT<<<(512 * 128 + 255) / 256, 256>>>(wk, bk, wq, bq, wv, bv, ws, bs);

    zero_cnt<<<(RN + 255) / 256, 256>>>();
    count_edges<<<(NEDGES + 255) / 256, 256>>>(ei, etype);
    scan_blocksum<<<NSCAN, SCAN_B>>>();
    scan_partials<<<1, SCAN_B>>>();
    scan_final<<<NSCAN, SCAN_B>>>();
    scatter_edges<<<(NEDGES + 255) / 256, 256>>>(ei, etype);

    xsplit<<<(NNODES * 32 + 255) / 256, 256>>>(x);
    agg_split<<<RN / 8, 256>>>(x);

    gemm1_wmma<<<MT, 256, GSMEM>>>(bias1);
    gemm2_wmma<<<dim3(MT, 4), 256, GSMEM>>>();

    gate_kernel<<<(NNODES + 7) / 8, 256>>>(out);
}

// round 6
// speedup vs baseline: 1.9993x; 1.1686x over previous
#include <cuda_runtime.h>
#include <cuda_fp16.h>
#include <mma.h>
#include <cstdint>

using namespace nvcuda;

#define NNODES 50000
#define NEDGES 600000
#define NREL   8
#define NBASIS 32
#define RN     (NREL * NNODES)
#define SCAN_B 1024
#define NSCAN  ((RN + SCAN_B - 1) / SCAN_B)
#define NK     1152
#define MT     ((NNODES + 127) / 128)    // 391
#define MPAD   (MT * 128)                // 50048

// ---------------- static device scratch ----------------
static __device__ __align__(16) __half d_Ahi[(size_t)NNODES * NK];
static __device__ __align__(16) __half d_Alo[(size_t)NNODES * NK];
static __device__ __align__(16) __half d_Bh[128 * NK];           // [n][k]
static __device__ __align__(16) __half d_Ch[512 * 128];          // [n][k]
static __device__ __align__(16) float d_bcat[512];
static __device__ __align__(16) __half d_hhi[(size_t)NNODES * 128];
static __device__ __align__(16) __half d_hlo[(size_t)NNODES * 128];
static __device__ __align__(16) float d_P[2 * (size_t)MPAD * 128];  // split-K partials
static __device__ __align__(16) float d_kskip[(size_t)NNODES * 256];
static __device__ __align__(16) float d_qv[(size_t)NNODES * 256];
static __device__ int d_cnt[RN];
static __device__ int d_off[RN + 1];
static __device__ int d_cur[RN];
static __device__ int d_ssrc[NEDGES];
static __device__ int d_part[SCAN_B];
static __device__ int d_ppre[SCAN_B];

// ---------------- helpers ----------------
__device__ __forceinline__ void split2h(float v, __half& hi, __half& lo) {
    hi = __float2half(v);
    lo = __float2half(v - __half2float(hi));
}
__device__ __forceinline__ float sigf(float z) { return 1.0f / (1.0f + __expf(-z)); }
__device__ __forceinline__ uint32_t smem_u32(const void* p) {
    uint32_t a;
    asm("{ .reg .u64 t; cvta.to.shared.u64 t, %1; cvt.u32.u64 %0, t; }" : "=r"(a) : "l"(p));
    return a;
}
__device__ __forceinline__ void cpa(uint32_t d, const void* s, int srcsz) {
    asm volatile("cp.async.cg.shared.global [%0], [%1], 16, %2;"
                 :: "r"(d), "l"(s), "r"(srcsz) : "memory");
}
#define CP_COMMIT() asm volatile("cp.async.commit_group;" ::: "memory")
#define CP_WAIT2()  asm volatile("cp.async.wait_group 2;" ::: "memory")
#define CP_WAIT0()  asm volatile("cp.async.wait_group 0;" ::: "memory")

// ---------------- weight prep ----------------
__global__ void build_BT(const float* __restrict__ comp, const float* __restrict__ basis,
                         const float* __restrict__ root) {
    int idx = blockIdx.x * blockDim.x + threadIdx.x;
    if (idx >= 128 * NK) return;
    int n = idx / NK, k = idx % NK;
    float w;
    if (k < 1024) {
        int r = k >> 7, i = k & 127;
        float s = 0.0f;
        #pragma unroll
        for (int b = 0; b < NBASIS; b++)
            s += comp[r * NBASIS + b] * basis[(b * 128 + i) * 128 + n];
        w = s;
    } else {
        w = root[(k - 1024) * 128 + n];
    }
    d_Bh[idx] = __float2half(w);
}

__global__ void pack_CT(const float* wk, const float* bk, const float* wq, const float* bq,
                        const float* wv, const float* bv, const float* ws, const float* bs) {
    int idx = blockIdx.x * blockDim.x + threadIdx.x;
    if (idx >= 512 * 128) return;
    int n = idx >> 7, k = idx & 127;
    int sel = n >> 7, cc = n & 127;
    const float* W = (sel == 0) ? wk : (sel == 1) ? wq : (sel == 2) ? wv : ws;
    d_Ch[idx] = __float2half(W[k * 128 + cc]);
    if (k == 0) {
        const float* B = (sel == 0) ? bk : (sel == 1) ? bq : (sel == 2) ? bv : bs;
        d_bcat[n] = B[cc];
    }
}

// ---------------- CSR build ----------------
__global__ void zero_cnt() {
    int i = blockIdx.x * blockDim.x + threadIdx.x;
    if (i < RN) d_cnt[i] = 0;
}
__global__ void count_edges(const int* __restrict__ ei, const int* __restrict__ etype) {
    int e = blockIdx.x * blockDim.x + threadIdx.x;
    if (e >= NEDGES) return;
    atomicAdd(&d_cnt[ei[NEDGES + e] * NREL + etype[e]], 1);
}
__global__ void scan_blocksum() {
    __shared__ int s[SCAN_B];
    int tid = threadIdx.x, gid = blockIdx.x * SCAN_B + tid;
    s[tid] = (gid < RN) ? d_cnt[gid] : 0;
    __syncthreads();
    for (int o = SCAN_B / 2; o > 0; o >>= 1) { if (tid < o) s[tid] += s[tid + o]; __syncthreads(); }
    if (tid == 0) d_part[blockIdx.x] = s[0];
}
__global__ void scan_partials() {
    __shared__ int s[SCAN_B];
    int tid = threadIdx.x;
    int v = (tid < NSCAN) ? d_part[tid] : 0;
    s[tid] = v; __syncthreads();
    for (int o = 1; o < SCAN_B; o <<= 1) {
        int t = (tid >= o) ? s[tid - o] : 0; __syncthreads();
        s[tid] += t; __syncthreads();
    }
    d_ppre[tid] = s[tid] - v;
}
__global__ void scan_final() {
    __shared__ int s[SCAN_B];
    int tid = threadIdx.x, gid = blockIdx.x * SCAN_B + tid;
    int v = (gid < RN) ? d_cnt[gid] : 0;
    s[tid] = v; __syncthreads();
    for (int o = 1; o < SCAN_B; o <<= 1) {
        int t = (tid >= o) ? s[tid - o] : 0; __syncthreads();
        s[tid] += t; __syncthreads();
    }
    int ex = s[tid] - v + d_ppre[blockIdx.x];
    if (gid < RN) {
        d_off[gid] = ex; d_cur[gid] = ex;
        if (gid == RN - 1) d_off[RN] = ex + v;
    }
}
__global__ void scatter_edges(const int* __restrict__ ei, const int* __restrict__ etype) {
    int e = blockIdx.x * blockDim.x + threadIdx.x;
    if (e >= NEDGES) return;
    int pos = atomicAdd(&d_cur[ei[NEDGES + e] * NREL + etype[e]], 1);
    d_ssrc[pos] = ei[e];
}

// ---------------- gather: per-(dst,rel) mean -> split-fp16 A cols 0..1023 ----------------
__global__ void agg_split(const float* __restrict__ x) {
    int seg = blockIdx.x * 8 + (threadIdx.x >> 5);
    if (seg >= RN) return;
    int lane = threadIdx.x & 31;
    int beg = d_off[seg], end = d_off[seg + 1];
    int dst = seg >> 3, r = seg & 7;
    const float4* x4 = reinterpret_cast<const float4*>(x);
    float4 acc = make_float4(0.f, 0.f, 0.f, 0.f);
    for (int e = beg; e < end; e++) {
        float4 v = __ldg(&x4[(size_t)d_ssrc[e] * 32 + lane]);
        acc.x += v.x; acc.y += v.y; acc.z += v.z; acc.w += v.w;
    }
    float inv = (end > beg) ? 1.0f / (float)(end - beg) : 0.0f;
    float vv[4] = { acc.x * inv, acc.y * inv, acc.z * inv, acc.w * inv };
    __align__(8) __half hi[4], lo[4];
    #pragma unroll
    for (int j = 0; j < 4; j++) split2h(vv[j], hi[j], lo[j]);
    size_t b = (size_t)dst * NK + r * 128 + lane * 4;
    *(uint2*)&d_Ahi[b] = *(uint2*)hi;
    *(uint2*)&d_Alo[b] = *(uint2*)lo;
}

__global__ void xsplit(const float* __restrict__ x) {
    int idx = blockIdx.x * blockDim.x + threadIdx.x;
    if (idx >= NNODES * 32) return;
    int row = idx >> 5, l = idx & 31;
    float4 v = reinterpret_cast<const float4*>(x)[(size_t)row * 32 + l];
    float vv[4] = { v.x, v.y, v.z, v.w };
    __align__(8) __half hi[4], lo[4];
    #pragma unroll
    for (int j = 0; j < 4; j++) split2h(vv[j], hi[j], lo[j]);
    size_t b = (size_t)row * NK + 1024 + l * 4;
    *(uint2*)&d_Ahi[b] = *(uint2*)hi;
    *(uint2*)&d_Alo[b] = *(uint2*)lo;
}

// ---------------- wmma GEMMs: 2-product fp16 split, 3-stage cp.async ----------------
typedef wmma::fragment<wmma::matrix_a, 16, 16, 16, __half, wmma::row_major> FragA;
typedef wmma::fragment<wmma::matrix_b, 16, 16, 16, __half, wmma::col_major> FragB;
typedef wmma::fragment<wmma::accumulator, 16, 16, 16, float> FragC;

// stage (bytes): A_hi[128*40*2=10240] | A_lo[10240] | B[10240] = 30720
#define STAGE_B 30720
#define NSTG    3
#define GSMEM   (NSTG * STAGE_B)     // 92160; epilogue buf 67584 fits

__device__ __forceinline__ void mma_block(char* sm, int st, int wm, int wn, FragC acc[2][4]) {
    __half* p = (__half*)(sm + st * STAGE_B);
    #pragma unroll
    for (int kk = 0; kk < 32; kk += 16) {
        FragA fah[2], fal[2];
        #pragma unroll
        for (int i = 0; i < 2; i++) {
            wmma::load_matrix_sync(fah[i], p + (wm + i * 16) * 40 + kk, 40);
            wmma::load_matrix_sync(fal[i], p + 5120 + (wm + i * 16) * 40 + kk, 40);
        }
        #pragma unroll
        for (int j = 0; j < 4; j++) {
            FragB fb;
            wmma::load_matrix_sync(fb, p + 10240 + (wn + j * 16) * 40 + kk, 40);
            #pragma unroll
            for (int i = 0; i < 2; i++) {
                wmma::mma_sync(acc[i][j], fah[i], fb, acc[i][j]);
                wmma::mma_sync(acc[i][j], fal[i], fb, acc[i][j]);
            }
        }
    }
}

// GEMM1 split-K: blockIdx.y = kz (0/1), chunks [kz*18, kz*18+18); partials -> d_P
__global__ void __launch_bounds__(256, 2) gemm1_wmma() {
    extern __shared__ __align__(16) char sm[];
    uint32_t sa = smem_u32(sm);
    int tid = threadIdx.x, wid = tid >> 5;
    int m0 = blockIdx.x << 7;
    int kz = blockIdx.y;
    int wm = (wid & 3) << 5;
    int wn = (wid >> 2) << 6;

    FragC acc[2][4];
    #pragma unroll
    for (int i = 0; i < 2; i++)
        #pragma unroll
        for (int j = 0; j < 4; j++) wmma::fill_fragment(acc[i][j], 0.0f);

    auto issue = [&](int ch, int st) {
        int k0 = ch << 5;
        uint32_t so = sa + st * STAGE_B;
        #pragma unroll
        for (int t = tid; t < 512; t += 256) {
            int row = t >> 2, c8 = (t & 3) << 3;
            int gr = m0 + row;
            int pr = (gr < NNODES) ? 16 : 0;
            int grc = (gr < NNODES) ? gr : 0;
            size_t ga = (size_t)grc * NK + k0 + c8;
            uint32_t ds = so + row * 80 + c8 * 2;
            cpa(ds,         d_Ahi + ga, pr);
            cpa(ds + 10240, d_Alo + ga, pr);
            size_t gb = (size_t)row * NK + k0 + c8;
            cpa(ds + 20480, d_Bh + gb, 16);
        }
    };

    int base = kz * 18;
    issue(base + 0, 0); CP_COMMIT();
    issue(base + 1, 1); CP_COMMIT();
    for (int ch = 0; ch < 18; ch++) {
        if (ch + 2 < 18) issue(base + ch + 2, (ch + 2) % NSTG);
        CP_COMMIT();
        CP_WAIT2();
        __syncthreads();
        mma_block(sm, ch % NSTG, wm, wn, acc);
        __syncthreads();
    }
    CP_WAIT0();

    // direct partial store (padded buffer -> no OOB)
    float* P = d_P + (size_t)kz * MPAD * 128;
    #pragma unroll
    for (int i = 0; i < 2; i++)
        #pragma unroll
        for (int j = 0; j < 4; j++)
            wmma::store_matrix_sync(&P[(size_t)(m0 + wm + i * 16) * 128 + wn + j * 16],
                                    acc[i][j], 128, wmma::mem_row_major);
}

// h = P0 + P1 + bias1 -> split fp16
__global__ void finish_h(const float* __restrict__ bias1) {
    int idx = blockIdx.x * blockDim.x + threadIdx.x;
    if (idx >= NNODES * 32) return;
    int row = idx >> 5, c4 = (idx & 31) << 2;
    size_t o = (size_t)row * 128 + c4;
    float4 a = *(const float4*)&d_P[o];
    float4 b = *(const float4*)&d_P[(size_t)MPAD * 128 + o];
    float vv[4] = { a.x + b.x + bias1[c4],     a.y + b.y + bias1[c4 + 1],
                    a.z + b.z + bias1[c4 + 2], a.w + b.w + bias1[c4 + 3] };
    __align__(8) __half hi[4], lo[4];
    #pragma unroll
    for (int j = 0; j < 4; j++) split2h(vv[j], hi[j], lo[j]);
    *(uint2*)&d_hhi[o] = *(uint2*)hi;
    *(uint2*)&d_hlo[o] = *(uint2*)lo;
}

__global__ void __launch_bounds__(256, 2) gemm2_wmma() {
    extern __shared__ __align__(16) char sm[];
    uint32_t sa = smem_u32(sm);
    int tid = threadIdx.x, wid = tid >> 5;
    int m0 = blockIdx.x << 7;
    int n0 = blockIdx.y << 7;
    int wm = (wid & 3) << 5;
    int wn = (wid >> 2) << 6;

    FragC acc[2][4];
    #pragma unroll
    for (int i = 0; i < 2; i++)
        #pragma unroll
        for (int j = 0; j < 4; j++) wmma::fill_fragment(acc[i][j], 0.0f);

    auto issue = [&](int ch, int st) {
        int k0 = ch << 5;
        uint32_t so = sa + st * STAGE_B;
        #pragma unroll
        for (int t = tid; t < 512; t += 256) {
            int row = t >> 2, c8 = (t & 3) << 3;
            int gr = m0 + row;
            int pr = (gr < NNODES) ? 16 : 0;
            int grc = (gr < NNODES) ? gr : 0;
            size_t ga = (size_t)grc * 128 + k0 + c8;
            uint32_t ds = so + row * 80 + c8 * 2;
            cpa(ds,         d_hhi + ga, pr);
            cpa(ds + 10240, d_hlo + ga, pr);
            size_t gb = (size_t)(n0 + row) * 128 + k0 + c8;
            cpa(ds + 20480, d_Ch + gb, 16);
        }
    };

    issue(0, 0); CP_COMMIT();
    issue(1, 1); CP_COMMIT();
    for (int ch = 0; ch < 4; ch++) {
        if (ch + 2 < 4) issue(ch + 2, (ch + 2) % NSTG);
        CP_COMMIT();
        CP_WAIT2();
        __syncthreads();
        mma_block(sm, ch % NSTG, wm, wn, acc);
        __syncthreads();
    }
    CP_WAIT0();

    float* sC = (float*)sm;
    #pragma unroll
    for (int i = 0; i < 2; i++)
        #pragma unroll
        for (int j = 0; j < 4; j++)
            wmma::store_matrix_sync(&sC[(wm + i * 16) * 132 + wn + j * 16],
                                    acc[i][j], 132, wmma::mem_row_major);
    __syncthreads();
    int sel = n0 >> 7;
    for (int t = tid; t < 4096; t += 256) {
        int row = t >> 5, c4 = (t & 31) << 2;
        int gr = m0 + row;
        if (gr >= NNODES) continue;
        const float* p = &sC[row * 132 + c4];
        int c = n0 + c4;
        float4 v = make_float4(p[0] + d_bcat[c], p[1] + d_bcat[c + 1],
                               p[2] + d_bcat[c + 2], p[3] + d_bcat[c + 3]);
        float* dst;
        if (sel == 0)      dst = &d_kskip[(size_t)gr * 256 + c4];
        else if (sel == 1) dst = &d_qv[(size_t)gr * 256 + c4];
        else if (sel == 2) dst = &d_qv[(size_t)gr * 256 + 128 + c4];
        else               dst = &d_kskip[(size_t)gr * 256 + 128 + c4];
        *(float4*)dst = v;
    }
}

// ---------------- gate ----------------
__global__ void gate_kernel(float* __restrict__ out) {
    int dst = blockIdx.x * 8 + (threadIdx.x >> 5);
    if (dst >= NNODES) return;
    int lane = threadIdx.x & 31;
    const float4* ks4 = reinterpret_cast<const float4*>(d_kskip);
    const float4* qv4 = reinterpret_cast<const float4*>(d_qv);
    float4 kd  = ks4[(size_t)dst * 64 + lane];
    float4 acc = ks4[(size_t)dst * 64 + 32 + lane];
    int beg = d_off[dst * NREL];
    int end = d_off[dst * NREL + NREL];
    for (int e = beg; e < end; e++) {
        int s = d_ssrc[e];
        float4 q = __ldg(&qv4[(size_t)s * 64 + lane]);
        float4 v = __ldg(&qv4[(size_t)s * 64 + 32 + lane]);
        acc.x += v.x * sigf(kd.x + q.x);
        acc.y += v.y * sigf(kd.y + q.y);
        acc.z += v.z * sigf(kd.z + q.z);
        acc.w += v.w * sigf(kd.w + q.w);
    }
    reinterpret_cast<float4*>(out)[(size_t)dst * 32 + lane] = acc;
}

// ---------------- launcher ----------------
extern "C" void kernel_launch(void* const* d_in, const int* in_sizes, int n_in,
                              void* d_out, int out_size) {
    const float* x     = (const float*)d_in[0];
    const int*   ei    = (const int*)  d_in[1];
    const int*   etype = (const int*)  d_in[3];
    const float* basis = (const float*)d_in[4];
    const float* comp  = (const float*)d_in[5];
    const float* root  = (const float*)d_in[6];
    const float* bias1 = (const float*)d_in[7];
    const float* wk = (const float*)d_in[8];  const float* bk = (const float*)d_in[9];
    const float* wq = (const float*)d_in[10]; const float* bq = (const float*)d_in[11];
    const float* wv = (const float*)d_in[12]; const float* bv = (const float*)d_in[13];
    const float* ws = (const float*)d_in[14]; const float* bs = (const float*)d_in[15];
    float* out = (float*)d_out;

    cudaFuncSetAttribute(gemm1_wmma, cudaFuncAttributeMaxDynamicSharedMemorySize, GSMEM);
    cudaFuncSetAttribute(gemm2_wmma, cudaFuncAttributeMaxDynamicSharedMemorySize, GSMEM);

    build_BT<<<(128 * NK + 255) / 256, 256>>>(comp, basis, root);
    pack_CT<<<(512 * 128 + 255) / 256, 256>>>(wk, bk, wq, bq, wv, bv, ws, bs);

    zero_cnt<<<(RN + 255) / 256, 256>>>();
    count_edges<<<(NEDGES + 255) / 256, 256>>>(ei, etype);
    scan_blocksum<<<NSCAN, SCAN_B>>>();
    scan_partials<<<1, SCAN_B>>>();
    scan_final<<<NSCAN, SCAN_B>>>();
    scatter_edges<<<(NEDGES + 255) / 256, 256>>>(ei, etype);

    xsplit<<<(NNODES * 32 + 255) / 256, 256>>>(x);
    agg_split<<<RN / 8, 256>>>(x);

    gemm1_wmma<<<dim3(MT, 2), 256, GSMEM>>>();
    finish_h<<<(NNODES * 32 + 255) / 256, 256>>>(bias1);
    gemm2_wmma<<<dim3(MT, 4), 256, GSMEM>>>();

    gate_kernel<<<(NNODES + 7) / 8, 256>>>(out);
}